// round 1
// baseline (speedup 1.0000x reference)
#include <cuda_runtime.h>
#include <math.h>

#define T_OBS   64
#define T_UNOBS 32
#define B       4096
#define D       4
#define H       256
#define G3      768   // 3*H

// ---------------- scratch (static device buffers; no allocation) ----------------
__device__ __align__(128) float g_H1[(size_t)T_OBS * B * H];  // stem layer-1 out (256 MB)
__device__ __align__(128) float g_Wc[G3 * H];                 // wi @ W2 folded weight
__device__ __align__(128) float g_bc[G3];                     // bi + wi @ b2
__device__ __align__(128) float g_h[B * H];                   // hidden state
__device__ __align__(128) float g_G[(size_t)B * 2 * G3];      // per-step gates [gx | gh]

// ---------------- init hidden to zero ----------------
__global__ void zero_h_kernel() {
    int idx = blockIdx.x * blockDim.x + threadIdx.x;
    g_h[idx] = 0.f;
}

// ---------------- fold Wc = wi @ W2, bc = bi + wi @ b2 ----------------
__global__ void wc_kernel(const float* __restrict__ wi, const float* __restrict__ w2,
                          const float* __restrict__ b2, const float* __restrict__ bi) {
    int j = blockIdx.x;   // 0..767 (gate row)
    int k = threadIdx.x;  // 0..255 (input col)
    float acc = 0.f;
    for (int m = 0; m < H; m++)
        acc = fmaf(wi[j * H + m], w2[m * H + k], acc);
    g_Wc[j * H + k] = acc;
    if (k == 0) {
        float a = bi[j];
        for (int m = 0; m < H; m++)
            a = fmaf(wi[j * H + m], b2[m], a);
        g_bc[j] = a;
    }
}

// ---------------- stem layer 1: h1 = leaky_relu([x, dt] @ W1^T + b1) ----------------
__global__ void stem_kernel(const float* __restrict__ x_obs, const float* __restrict__ t_obs,
                            const float* __restrict__ w1, const float* __restrict__ b1) {
    int row = blockIdx.x;      // t*B + b, 0..262143
    int j = threadIdx.x;       // 0..255
    __shared__ float xt[8];
    if (j < 4) {
        xt[j] = x_obs[(size_t)row * 4 + j];
    } else if (j == 4) {
        int t = row >> 12;     // row / 4096
        xt[4] = (t == 0) ? 0.f : (t_obs[row] - t_obs[row - B]);
    }
    __syncthreads();
    float acc = b1[j];
#pragma unroll
    for (int k = 0; k < 5; k++)
        acc = fmaf(w1[j * 5 + k], xt[k], acc);
    g_H1[(size_t)row * H + j] = (acc > 0.f) ? acc : 0.01f * acc;
}

// ---------------- per-step gates GEMM ----------------
// Computes G[b, 0:768]   = A0[b,:] @ W0^T + bias0   (gx path)
//          G[b, 768:1536]= h[b,:]  @ wh^T + bh      (gh path)
// obs_t >= 0:  A0 = g_H1[obs_t], W0 = g_Wc, bias0 = g_bc
// obs_t <  0:  A0 = g_h (AR: z == h), W0 = wi, bias0 = bi
// Tile: 128x128x16, 256 threads, 8x8 per thread.
__global__ __launch_bounds__(256, 2) void gemm_gates(
    int obs_t,
    const float* __restrict__ wi, const float* __restrict__ wh,
    const float* __restrict__ bi, const float* __restrict__ bh) {
    constexpr int BM = 128, BN = 128, BK = 16;
    __shared__ float As[BK][BM];
    __shared__ float Bs[BK][BN];

    int tid = threadIdx.x;
    int tn = blockIdx.x;   // 0..11 (6 gx tiles + 6 gh tiles)
    int tm = blockIdx.y;   // 0..31

    bool second = (tn >= 6);
    const float* A;
    const float* W;
    const float* bias;
    if (second)          { A = g_h;                              W = wh;   bias = bh;   }
    else if (obs_t >= 0) { A = g_H1 + (size_t)obs_t * B * H;     W = g_Wc; bias = g_bc; }
    else                 { A = g_h;                              W = wi;   bias = bi;   }

    int nbase = (second ? tn - 6 : tn) * BN;  // within [0,768)
    int mbase = tm * BM;
    int gcolbase = (second ? G3 : 0) + nbase;

    float acc[8][8] = {};

    for (int k0 = 0; k0 < H; k0 += BK) {
        // load A tile [BM x BK] -> As[k][m]   (512 float4 slots, 2 per thread)
#pragma unroll
        for (int l = 0; l < 2; l++) {
            int s = tid + l * 256;
            int m = s >> 2, kq = s & 3;
            float4 v = *(const float4*)(A + (size_t)(mbase + m) * H + k0 + kq * 4);
            As[kq * 4 + 0][m] = v.x; As[kq * 4 + 1][m] = v.y;
            As[kq * 4 + 2][m] = v.z; As[kq * 4 + 3][m] = v.w;
        }
        // load W tile [BN x BK] -> Bs[k][n]
#pragma unroll
        for (int l = 0; l < 2; l++) {
            int s = tid + l * 256;
            int n = s >> 2, kq = s & 3;
            float4 v = *(const float4*)(W + (size_t)(nbase + n) * H + k0 + kq * 4);
            Bs[kq * 4 + 0][n] = v.x; Bs[kq * 4 + 1][n] = v.y;
            Bs[kq * 4 + 2][n] = v.z; Bs[kq * 4 + 3][n] = v.w;
        }
        __syncthreads();

        int ty = tid >> 4, tx = tid & 15;
#pragma unroll
        for (int k = 0; k < BK; k++) {
            float a[8], b[8];
#pragma unroll
            for (int i = 0; i < 8; i++) a[i] = As[k][ty * 8 + i];
#pragma unroll
            for (int j = 0; j < 8; j++) b[j] = Bs[k][tx * 8 + j];
#pragma unroll
            for (int i = 0; i < 8; i++)
#pragma unroll
                for (int j = 0; j < 8; j++)
                    acc[i][j] = fmaf(a[i], b[j], acc[i][j]);
        }
        __syncthreads();
    }

    int ty = tid >> 4, tx = tid & 15;
    float bj[8];
#pragma unroll
    for (int j = 0; j < 8; j++) bj[j] = bias[nbase + tx * 8 + j];
#pragma unroll
    for (int i = 0; i < 8; i++) {
        int m = mbase + ty * 8 + i;
        float4 v0, v1;
        v0.x = acc[i][0] + bj[0]; v0.y = acc[i][1] + bj[1];
        v0.z = acc[i][2] + bj[2]; v0.w = acc[i][3] + bj[3];
        v1.x = acc[i][4] + bj[4]; v1.y = acc[i][5] + bj[5];
        v1.z = acc[i][6] + bj[6]; v1.w = acc[i][7] + bj[7];
        float* gp = g_G + (size_t)m * (2 * G3) + gcolbase + tx * 8;
        *(float4*)(gp)     = v0;
        *(float4*)(gp + 4) = v1;
    }
}

// ---------------- GRU gate elementwise (PyTorch order r,z,n) ----------------
__global__ void gru_update(float* __restrict__ zs_out) {
    int b = blockIdx.x, m = threadIdx.x;
    const float* g = g_G + (size_t)b * (2 * G3);
    float rx = g[m],       zx = g[H + m],       nx = g[2 * H + m];
    float rh = g[G3 + m],  zh = g[G3 + H + m],  nh = g[G3 + 2 * H + m];
    float r = 1.f / (1.f + expf(-(rx + rh)));
    float u = 1.f / (1.f + expf(-(zx + zh)));
    float n = tanhf(nx + r * nh);
    float hp = g_h[b * H + m];
    float hn = (1.f - u) * n + u * hp;
    g_h[b * H + m] = hn;
    if (zs_out) zs_out[(size_t)b * H + m] = hn;
}

// ---------------- head: x_hats = zs @ head_w^T + head_b ----------------
__global__ void head_kernel(const float* __restrict__ zs, const float* __restrict__ head_w,
                            const float* __restrict__ head_b, float* __restrict__ xh) {
    int row = blockIdx.x * 8 + (threadIdx.x >> 5);  // 0..131071
    int lane = threadIdx.x & 31;
    const float* z = zs + (size_t)row * H;
    float acc[4] = {0.f, 0.f, 0.f, 0.f};
    for (int c = lane; c < H; c += 32) {
        float zv = z[c];
#pragma unroll
        for (int d = 0; d < 4; d++)
            acc[d] = fmaf(zv, head_w[d * H + c], acc[d]);
    }
#pragma unroll
    for (int d = 0; d < 4; d++)
        for (int off = 16; off; off >>= 1)
            acc[d] += __shfl_xor_sync(0xFFFFFFFFu, acc[d], off);
    if (lane < 4)
        xh[(size_t)row * 4 + lane] = acc[lane] + head_b[lane];
}

// ---------------- launch ----------------
extern "C" void kernel_launch(void* const* d_in, const int* in_sizes, int n_in,
                              void* d_out, int out_size) {
    const float* x_obs   = (const float*)d_in[0];
    const float* t_obs   = (const float*)d_in[1];
    // d_in[2] = t_unobs: only its length (32) matters, unused
    const float* stem_w1 = (const float*)d_in[3];
    const float* stem_b1 = (const float*)d_in[4];
    const float* stem_w2 = (const float*)d_in[5];
    const float* stem_b2 = (const float*)d_in[6];
    const float* gru_wi  = (const float*)d_in[7];
    const float* gru_wh  = (const float*)d_in[8];
    const float* gru_bi  = (const float*)d_in[9];
    const float* gru_bh  = (const float*)d_in[10];
    const float* head_w  = (const float*)d_in[11];
    const float* head_b  = (const float*)d_in[12];

    float* out    = (float*)d_out;
    float* x_hats = out;                                 // [32,4096,4]
    float* zs     = out + (size_t)T_UNOBS * B * D;       // [32,4096,256]

    zero_h_kernel<<<(B * H) / 256, 256>>>();
    wc_kernel<<<G3, H>>>(gru_wi, stem_w2, stem_b2, gru_bi);
    stem_kernel<<<T_OBS * B, H>>>(x_obs, t_obs, stem_w1, stem_b1);

    dim3 ggrid(12, 32);
    for (int t = 0; t < T_OBS; t++) {
        gemm_gates<<<ggrid, 256>>>(t, gru_wi, gru_wh, gru_bi, gru_bh);
        gru_update<<<B, H>>>((t == T_OBS - 1) ? zs : (float*)nullptr);  // zs[0] = z_last
    }
    for (int s = 1; s < T_UNOBS; s++) {
        gemm_gates<<<ggrid, 256>>>(-1, gru_wi, gru_wh, gru_bi, gru_bh);
        gru_update<<<B, H>>>(zs + (size_t)s * B * H);
    }

    head_kernel<<<(T_UNOBS * B) / 8, 256>>>(zs, head_w, head_b, x_hats);
}

// round 5
// speedup vs baseline: 2.3351x; 2.3351x over previous
#include <cuda_runtime.h>
#include <math.h>

#define T_OBS   64
#define T_UNOBS 32
#define B       4096
#define D       4
#define H       256
#define G3      768   // 3*H

// ---------------- scratch (static device buffers; no allocation) ----------------
__device__ __align__(128) float g_H1[(size_t)T_OBS * B * H];  // stem layer-1 out
__device__ __align__(128) float g_Wc[G3 * H];                 // wi @ W2 folded weight
__device__ __align__(128) float g_bc[G3];                     // bi + wi @ b2
__device__ __align__(128) float g_h[B * H];                   // hidden state
__device__ __align__(128) float g_G[(size_t)B * 2 * G3];      // per-step gates [gx | gh]

// ---------------- init hidden to zero ----------------
__global__ void zero_h_kernel() {
    int idx = blockIdx.x * blockDim.x + threadIdx.x;
    g_h[idx] = 0.f;
}

// ---------------- fold Wc = wi @ W2, bc = bi + wi @ b2 (fp32, tiny) ----------------
__global__ void wc_kernel(const float* __restrict__ wi, const float* __restrict__ w2,
                          const float* __restrict__ b2, const float* __restrict__ bi) {
    int j = blockIdx.x;   // 0..767
    int k = threadIdx.x;  // 0..255
    float acc = 0.f;
    for (int m = 0; m < H; m++)
        acc = fmaf(wi[j * H + m], w2[m * H + k], acc);
    g_Wc[j * H + k] = acc;
    if (k == 0) {
        float a = bi[j];
        for (int m = 0; m < H; m++)
            a = fmaf(wi[j * H + m], b2[m], a);
        g_bc[j] = a;
    }
}

// ---------------- stem layer 1: h1 = leaky_relu([x, dt] @ W1^T + b1) ----------------
__global__ void stem_kernel(const float* __restrict__ x_obs, const float* __restrict__ t_obs,
                            const float* __restrict__ w1, const float* __restrict__ b1) {
    int row = blockIdx.x;      // t*B + b
    int j = threadIdx.x;       // 0..255
    __shared__ float xt[8];
    if (j < 4) {
        xt[j] = x_obs[(size_t)row * 4 + j];
    } else if (j == 4) {
        int t = row >> 12;
        xt[4] = (t == 0) ? 0.f : (t_obs[row] - t_obs[row - B]);
    }
    __syncthreads();
    float acc = b1[j];
#pragma unroll
    for (int k = 0; k < 5; k++)
        acc = fmaf(w1[j * 5 + k], xt[k], acc);
    g_H1[(size_t)row * H + j] = (acc > 0.f) ? acc : 0.01f * acc;
}

// ---------------- helpers: tf32 convert + mma ----------------
__device__ __forceinline__ unsigned f2tf32(float f) {
    unsigned u;
    asm("cvt.rna.tf32.f32 %0, %1;" : "=r"(u) : "f"(f));
    return u;
}

__device__ __forceinline__ void mma_tf32(float* c, const unsigned* a, const unsigned* b) {
    asm volatile(
        "mma.sync.aligned.m16n8k8.row.col.f32.tf32.tf32.f32 "
        "{%0,%1,%2,%3}, {%4,%5,%6,%7}, {%8,%9}, {%0,%1,%2,%3};"
        : "+f"(c[0]), "+f"(c[1]), "+f"(c[2]), "+f"(c[3])
        : "r"(a[0]), "r"(a[1]), "r"(a[2]), "r"(a[3]), "r"(b[0]), "r"(b[1]));
}

// ---------------- per-step gates GEMM (tensor cores, tf32) ----------------
// G[b, 0:768]    = A0[b,:] @ W0^T + bias0   (gx path, blocks tn 0..5)
// G[b, 768:1536] = h[b,:]  @ wh^T + bh      (gh path, blocks tn 6..11)
// Tile: BM=128, BN=128, BK=16. 8 warps, warp tile 32x64 (2 m-sub x 8 n-sub of m16n8k8).
__global__ __launch_bounds__(256, 2) void gemm_gates_tc(
    int obs_t,
    const float* __restrict__ wi, const float* __restrict__ wh,
    const float* __restrict__ bi, const float* __restrict__ bh) {
    constexpr int BK = 16;
    constexpr int LDS_PAD = 20;  // floats per row in smem (16 + 4 pad)
    __shared__ unsigned As[2][128][LDS_PAD];
    __shared__ unsigned Bs[2][128][LDS_PAD];

    int tid  = threadIdx.x;
    int warp = tid >> 5;
    int lane = tid & 31;
    int q = lane >> 2;          // 0..7
    int r = lane & 3;           // 0..3
    int wm = warp & 3;          // 0..3  (m position, 32 rows each)
    int wn = warp >> 2;         // 0..1  (n position, 64 cols each)

    int tn = blockIdx.x;        // 0..11
    int tm = blockIdx.y;        // 0..31

    bool second = (tn >= 6);
    const float* A;
    const float* W;
    const float* bias;
    if (second)          { A = g_h;                          W = wh;   bias = bh;   }
    else if (obs_t >= 0) { A = g_H1 + (size_t)obs_t * B * H; W = g_Wc; bias = g_bc; }
    else                 { A = g_h;                          W = wi;   bias = bi;   }

    int nbase = (second ? tn - 6 : tn) * 128;      // within [0,768)
    int mbase = tm * 128;
    int gcolbase = (second ? G3 : 0) + nbase;

    // global-load indexing: each thread loads 2 float4 from A and 2 from B per stage
    int rowL = tid >> 2;        // 0..63
    int kqL  = tid & 3;         // 0..3
    const float* Ap = A + (size_t)(mbase + rowL) * H + kqL * 4;
    const float* Wp = W + (size_t)(nbase + rowL) * H + kqL * 4;

    float acc[2][8][4];
#pragma unroll
    for (int mi = 0; mi < 2; mi++)
#pragma unroll
        for (int ni = 0; ni < 8; ni++)
#pragma unroll
            for (int j = 0; j < 4; j++) acc[mi][ni][j] = 0.f;

    // ---- prologue: load stage 0 ----
    float4 ra0 = *(const float4*)(Ap);
    float4 ra1 = *(const float4*)(Ap + (size_t)64 * H);
    float4 rb0 = *(const float4*)(Wp);
    float4 rb1 = *(const float4*)(Wp + (size_t)64 * H);
    {
        uint4 u;
        u.x = f2tf32(ra0.x); u.y = f2tf32(ra0.y); u.z = f2tf32(ra0.z); u.w = f2tf32(ra0.w);
        *(uint4*)&As[0][rowL][kqL * 4] = u;
        u.x = f2tf32(ra1.x); u.y = f2tf32(ra1.y); u.z = f2tf32(ra1.z); u.w = f2tf32(ra1.w);
        *(uint4*)&As[0][rowL + 64][kqL * 4] = u;
        u.x = f2tf32(rb0.x); u.y = f2tf32(rb0.y); u.z = f2tf32(rb0.z); u.w = f2tf32(rb0.w);
        *(uint4*)&Bs[0][rowL][kqL * 4] = u;
        u.x = f2tf32(rb1.x); u.y = f2tf32(rb1.y); u.z = f2tf32(rb1.z); u.w = f2tf32(rb1.w);
        *(uint4*)&Bs[0][rowL + 64][kqL * 4] = u;
    }
    __syncthreads();

    constexpr int NITER = H / BK;   // 16
#pragma unroll 1
    for (int kc = 0; kc < NITER; kc++) {
        int buf = kc & 1;
        // prefetch next stage into registers
        if (kc + 1 < NITER) {
            int k0 = (kc + 1) * BK;
            ra0 = *(const float4*)(Ap + k0);
            ra1 = *(const float4*)(Ap + (size_t)64 * H + k0);
            rb0 = *(const float4*)(Wp + k0);
            rb1 = *(const float4*)(Wp + (size_t)64 * H + k0);
        }

        // compute on current stage: 2 k-steps of 8
#pragma unroll
        for (int ks = 0; ks < 2; ks++) {
            int kk = ks * 8;
            unsigned af[2][4], bf[8][2];
#pragma unroll
            for (int mi = 0; mi < 2; mi++) {
                int rm = wm * 32 + mi * 16 + q;
                af[mi][0] = As[buf][rm][kk + r];
                af[mi][1] = As[buf][rm + 8][kk + r];
                af[mi][2] = As[buf][rm][kk + r + 4];
                af[mi][3] = As[buf][rm + 8][kk + r + 4];
            }
#pragma unroll
            for (int ni = 0; ni < 8; ni++) {
                int cn = wn * 64 + ni * 8 + q;
                bf[ni][0] = Bs[buf][cn][kk + r];
                bf[ni][1] = Bs[buf][cn][kk + r + 4];
            }
#pragma unroll
            for (int mi = 0; mi < 2; mi++)
#pragma unroll
                for (int ni = 0; ni < 8; ni++)
                    mma_tf32(acc[mi][ni], af[mi], bf[ni]);
        }

        // store next stage
        if (kc + 1 < NITER) {
            int nb = (kc + 1) & 1;
            uint4 u;
            u.x = f2tf32(ra0.x); u.y = f2tf32(ra0.y); u.z = f2tf32(ra0.z); u.w = f2tf32(ra0.w);
            *(uint4*)&As[nb][rowL][kqL * 4] = u;
            u.x = f2tf32(ra1.x); u.y = f2tf32(ra1.y); u.z = f2tf32(ra1.z); u.w = f2tf32(ra1.w);
            *(uint4*)&As[nb][rowL + 64][kqL * 4] = u;
            u.x = f2tf32(rb0.x); u.y = f2tf32(rb0.y); u.z = f2tf32(rb0.z); u.w = f2tf32(rb0.w);
            *(uint4*)&Bs[nb][rowL][kqL * 4] = u;
            u.x = f2tf32(rb1.x); u.y = f2tf32(rb1.y); u.z = f2tf32(rb1.z); u.w = f2tf32(rb1.w);
            *(uint4*)&Bs[nb][rowL + 64][kqL * 4] = u;
            __syncthreads();
        }
    }

    // ---- epilogue: bias + store to g_G ----
#pragma unroll
    for (int mi = 0; mi < 2; mi++) {
        int row = mbase + wm * 32 + mi * 16 + q;
#pragma unroll
        for (int ni = 0; ni < 8; ni++) {
            int cl = wn * 64 + ni * 8 + 2 * r;             // within [0,128)
            float b0 = bias[nbase + cl];
            float b1 = bias[nbase + cl + 1];
            float2 v0 = {acc[mi][ni][0] + b0, acc[mi][ni][1] + b1};
            float2 v1 = {acc[mi][ni][2] + b0, acc[mi][ni][3] + b1};
            *(float2*)&g_G[(size_t)row * (2 * G3) + gcolbase + cl]       = v0;
            *(float2*)&g_G[(size_t)(row + 8) * (2 * G3) + gcolbase + cl] = v1;
        }
    }
}

// ---------------- GRU gate elementwise (vectorized, PyTorch order r,z,n) ----------------
__global__ void gru_update(float* __restrict__ zs_out) {
    int i = blockIdx.x * blockDim.x + threadIdx.x;   // 0 .. B*H/4-1
    int b = i >> 6;
    int m4 = (i & 63) * 4;
    const float* g = g_G + (size_t)b * (2 * G3);
    float4 rx = *(const float4*)(g + m4);
    float4 zx = *(const float4*)(g + H + m4);
    float4 nx = *(const float4*)(g + 2 * H + m4);
    float4 rh = *(const float4*)(g + G3 + m4);
    float4 zh = *(const float4*)(g + G3 + H + m4);
    float4 nh = *(const float4*)(g + G3 + 2 * H + m4);
    float4 hp = *(const float4*)(g_h + (size_t)b * H + m4);
    float4 hn;
#pragma unroll
    for (int c = 0; c < 4; c++) {
        float rxv = (&rx.x)[c], zxv = (&zx.x)[c], nxv = (&nx.x)[c];
        float rhv = (&rh.x)[c], zhv = (&zh.x)[c], nhv = (&nh.x)[c];
        float hpv = (&hp.x)[c];
        float r = 1.f / (1.f + expf(-(rxv + rhv)));
        float u = 1.f / (1.f + expf(-(zxv + zhv)));
        float n = tanhf(nxv + r * nhv);
        (&hn.x)[c] = (1.f - u) * n + u * hpv;
    }
    *(float4*)(g_h + (size_t)b * H + m4) = hn;
    if (zs_out) *(float4*)(zs_out + (size_t)b * H + m4) = hn;
}

// ---------------- head: x_hats = zs @ head_w^T + head_b ----------------
__global__ void head_kernel(const float* __restrict__ zs, const float* __restrict__ head_w,
                            const float* __restrict__ head_b, float* __restrict__ xh) {
    int row = blockIdx.x * 8 + (threadIdx.x >> 5);
    int lane = threadIdx.x & 31;
    const float* z = zs + (size_t)row * H;
    float acc[4] = {0.f, 0.f, 0.f, 0.f};
    for (int c = lane; c < H; c += 32) {
        float zv = z[c];
#pragma unroll
        for (int d = 0; d < 4; d++)
            acc[d] = fmaf(zv, head_w[d * H + c], acc[d]);
    }
#pragma unroll
    for (int d = 0; d < 4; d++)
        for (int off = 16; off; off >>= 1)
            acc[d] += __shfl_xor_sync(0xFFFFFFFFu, acc[d], off);
    if (lane < 4)
        xh[(size_t)row * 4 + lane] = acc[lane] + head_b[lane];
}

// ---------------- launch ----------------
extern "C" void kernel_launch(void* const* d_in, const int* in_sizes, int n_in,
                              void* d_out, int out_size) {
    const float* x_obs   = (const float*)d_in[0];
    const float* t_obs   = (const float*)d_in[1];
    const float* stem_w1 = (const float*)d_in[3];
    const float* stem_b1 = (const float*)d_in[4];
    const float* stem_w2 = (const float*)d_in[5];
    const float* stem_b2 = (const float*)d_in[6];
    const float* gru_wi  = (const float*)d_in[7];
    const float* gru_wh  = (const float*)d_in[8];
    const float* gru_bi  = (const float*)d_in[9];
    const float* gru_bh  = (const float*)d_in[10];
    const float* head_w  = (const float*)d_in[11];
    const float* head_b  = (const float*)d_in[12];

    float* out    = (float*)d_out;
    float* x_hats = out;                                 // [32,4096,4]
    float* zs     = out + (size_t)T_UNOBS * B * D;       // [32,4096,256]

    zero_h_kernel<<<(B * H) / 256, 256>>>();
    wc_kernel<<<G3, H>>>(gru_wi, stem_w2, stem_b2, gru_bi);
    stem_kernel<<<T_OBS * B, H>>>(x_obs, t_obs, stem_w1, stem_b1);

    dim3 ggrid(12, 32);
    for (int t = 0; t < T_OBS; t++) {
        gemm_gates_tc<<<ggrid, 256>>>(t, gru_wi, gru_wh, gru_bi, gru_bh);
        gru_update<<<(B * H / 4) / 256, 256>>>((t == T_OBS - 1) ? zs : (float*)nullptr);
    }
    for (int s = 1; s < T_UNOBS; s++) {
        gemm_gates_tc<<<ggrid, 256>>>(-1, gru_wi, gru_wh, gru_bi, gru_bh);
        gru_update<<<(B * H / 4) / 256, 256>>>(zs + (size_t)s * B * H);
    }

    head_kernel<<<(T_UNOBS * B) / 8, 256>>>(zs, head_w, head_b, x_hats);
}